// round 11
// baseline (speedup 1.0000x reference)
#include <cuda_runtime.h>
#include <cuda_fp16.h>

#define S        128
#define N_LGN    17400
#define N_POST   50000
#define NNZ      800000
#define NBASIS   5
#define N_RECEPT 10
#define OUT_ROW  (N_POST * NBASIS)   // 250000
#define RPB      8                   // rows per block (spmm)
#define CAP      64                  // bucket capacity (Poisson(16); P(>64) ~ 1e-32)
#define PREP_BLKS 544                // ceil(17400/32)
#define SCAT_BLKS ((NNZ + 511) / 512)

// ---------------- device scratch (no allocations allowed) ----------------
// xTh: uint2 at [c*32 + lane] = 4 halves x[s = {lane, lane+32, lane+64, lane+96}][c]
// g_cnt invariant: zero before every kernel_launch execution (module-load zero
// init; k_spmm re-zeros each row after reading it).
__device__ __half g_xTh[N_LGN * S];
__device__ int    g_cnt[N_POST];
__device__ int4   g_meta[(size_t)N_POST * CAP];  // {col*256, h2(c0,c1), h2(c2,c3), h2(c4,0)}

typedef unsigned long long ull;
__device__ __forceinline__ void ffma2(ull &d, ull a, ull b) {
    asm("fma.rn.f32x2 %0, %1, %2, %0;" : "+l"(d) : "l"(a), "l"(b));
}
__device__ __forceinline__ ull pack2(float x, float y) {
    ull r;
    asm("mov.b64 %0, {%1, %2};" : "=l"(r) : "f"(x), "f"(y));
    return r;
}
__device__ __forceinline__ float2 unpack2(ull v) {
    float2 f;
    asm("mov.b64 {%0, %1}, %2;" : "=f"(f.x), "=f"(f.y) : "l"(v));
    return f;
}

// ------------- 1) fused: transpose/pack x  ||  bucket scatter -------------
__global__ void __launch_bounds__(512) k_pre(const float* __restrict__ x,
                                             const int2*  __restrict__ idx,
                                             const float* __restrict__ w,
                                             const int*   __restrict__ sids,
                                             const float* __restrict__ synw) {
    __shared__ float tile[S][33];
    __shared__ float fsh[N_RECEPT * NBASIS];
    int tid = threadIdx.x;

    if (blockIdx.x < PREP_BLKS) {
        // ---- transpose x[s][c] -> permuted fp16 pack ----
        int tx = tid & 31, ty = tid >> 5;    // (32,16)
        int c0 = blockIdx.x * 32;
        int c = c0 + tx;
        bool cok = (c < N_LGN);
        #pragma unroll
        for (int j = ty; j < S; j += 16)
            tile[j][tx] = cok ? x[j * N_LGN + c] : 0.f;
        __syncthreads();

        uint2* xb = (uint2*)g_xTh;
        #pragma unroll
        for (int cl = ty; cl < 32; cl += 16) {
            int cc = c0 + cl;
            if (cc < N_LGN) {
                __half2 h01 = __floats2half2_rn(tile[tx][cl],      tile[tx + 32][cl]);
                __half2 h23 = __floats2half2_rn(tile[tx + 64][cl], tile[tx + 96][cl]);
                uint2 v;
                v.x = *(unsigned int*)&h01;
                v.y = *(unsigned int*)&h23;
                xb[cc * 32 + tx] = v;
            }
        }
    } else {
        // ---- scatter: 16B meta with fp16 coefficients w*f[sid][r] ----
        if (tid < N_RECEPT * NBASIS) fsh[tid] = synw[tid];
        __syncthreads();
        int e = (blockIdx.x - PREP_BLKS) * 512 + tid;
        if (e >= NNZ) return;
        int2 rc = idx[e];
        float wv = w[e];
        const float* f = fsh + sids[e] * NBASIS;
        __half2 p01 = __floats2half2_rn(wv * f[0], wv * f[1]);
        __half2 p23 = __floats2half2_rn(wv * f[2], wv * f[3]);
        __half2 p4  = __floats2half2_rn(wv * f[4], 0.f);
        int p = atomicAdd(&g_cnt[rc.x], 1);
        if (p < CAP)
            g_meta[(size_t)rc.x * CAP + p] =
                make_int4(rc.y * 256, *(int*)&p01, *(int*)&p23, *(int*)&p4);
    }
}

// ---------------- per-edge math: 1 LDS.128 + 1 LDG.64 + f32x2 -------------
__device__ __forceinline__ void edge_math(int4 m, uint2 xh, ull acc[NBASIS][2]) {
    float2 x01 = __half22float2(*(__half2*)&xh.x);   // s = lane, lane+32
    float2 x23 = __half22float2(*(__half2*)&xh.y);   // s = lane+64, lane+96
    ull xa = pack2(x01.x, x01.y);
    ull xc = pack2(x23.x, x23.y);
    float2 c01 = __half22float2(*(__half2*)&m.y);
    float2 c23 = __half22float2(*(__half2*)&m.z);
    float  c4  = __low2float(*(__half2*)&m.w);
    ull f0 = pack2(c01.x, c01.x);
    ull f1 = pack2(c01.y, c01.y);
    ull f2 = pack2(c23.x, c23.x);
    ull f3 = pack2(c23.y, c23.y);
    ull f4 = pack2(c4,    c4);
    ffma2(acc[0][0], xa, f0); ffma2(acc[0][1], xc, f0);
    ffma2(acc[1][0], xa, f1); ffma2(acc[1][1], xc, f1);
    ffma2(acc[2][0], xa, f2); ffma2(acc[2][1], xc, f2);
    ffma2(acc[3][0], xa, f3); ffma2(acc[3][1], xc, f3);
    ffma2(acc[4][0], xa, f4); ffma2(acc[4][1], xc, f4);
}

// ---------------- 2) main SpMM: 128 thr, 4 warps x 2 rows ----------------
__global__ void __launch_bounds__(128, 8) k_spmm(float* __restrict__ out) {
    __shared__ __align__(16) float sh[S * 44];   // staging, 16B-aligned rows
    __shared__ __align__(16) int4  msh[4 * CAP]; // per-warp meta buffers (4KB)
    int tid  = threadIdx.x;
    int warp = tid >> 5;
    int lane = tid & 31;
    int n0 = blockIdx.x * RPB;
    const char* xlane = (const char*)g_xTh + lane * 8;
    int4* mb = msh + warp * CAP;

    #pragma unroll
    for (int rr = 0; rr < 2; rr++) {
        int n = n0 + warp * 2 + rr;
        int len = g_cnt[n];
        if (lane == 0) g_cnt[n] = 0;    // restore invariant for next replay
        if (len > CAP) len = CAP;
        const int4* pm = g_meta + (size_t)n * CAP;

        // copy this row's meta into the warp's smem buffer (lane-strided vec)
        for (int sg = 0; sg * 32 < len; sg++)
            mb[sg * 32 + lane] = __ldg(pm + sg * 32 + lane);
        __syncwarp();

        ull acc[NBASIS][2];
        #pragma unroll
        for (int r = 0; r < NBASIS; r++) { acc[r][0] = 0ull; acc[r][1] = 0ull; }

        int j = 0;
        #pragma unroll 1
        for (; j + 4 <= len; j += 4) {
            int4  m[4];
            uint2 xv[4];
            #pragma unroll
            for (int t = 0; t < 4; t++) m[t] = mb[j + t];           // bcast LDS.128
            #pragma unroll
            for (int t = 0; t < 4; t++)
                xv[t] = __ldg((const uint2*)(xlane + m[t].x));      // MLP 4
            #pragma unroll
            for (int t = 0; t < 4; t++) edge_math(m[t], xv[t], acc);
        }
        for (; j < len; j++) {
            int4  m  = mb[j];
            uint2 xv = __ldg((const uint2*)(xlane + m.x));
            edge_math(m, xv, acc);
        }

        // stage row: lane's values are s = {lane, +32, +64, +96}
        int rl = (warp * 2 + rr) * NBASIS;
        #pragma unroll
        for (int r = 0; r < NBASIS; r++) {
            float2 lo = unpack2(acc[r][0]);
            float2 hi = unpack2(acc[r][1]);
            sh[(lane      ) * 44 + rl + r] = lo.x;
            sh[(lane + 32 ) * 44 + rl + r] = lo.y;
            sh[(lane + 64 ) * 44 + rl + r] = hi.x;
            sh[(lane + 96 ) * 44 + rl + r] = hi.y;
        }
    }
    __syncthreads();

    // vectorized write-out: 1280 float4 = 128 s x 10 q; 10 iters per thread
    const float4* sh4 = (const float4*)sh;           // 11 float4 per s-row
    float* op = out + (size_t)n0 * NBASIS;
    #pragma unroll
    for (int it = 0; it < 10; it++) {
        int idx = it * 128 + tid;
        int s = idx / 10;
        int q = idx - s * 10;
        float4 v = sh4[s * 11 + q];
        *(float4*)(op + (size_t)s * OUT_ROW + q * 4) = v;
    }
}

// ---------------- launch ----------------
extern "C" void kernel_launch(void* const* d_in, const int* in_sizes, int n_in,
                              void* d_out, int out_size) {
    const float* inp     = (const float*)d_in[0];
    const int2*  indices = (const int2*)d_in[1];
    const float* weights = (const float*)d_in[2];
    const float* synw    = (const float*)d_in[3];
    const int*   sids    = (const int*)d_in[4];
    float*       out     = (float*)d_out;
    (void)in_sizes; (void)n_in; (void)out_size;

    k_pre<<<PREP_BLKS + SCAT_BLKS, 512>>>(inp, indices, weights, sids, synw);
    k_spmm<<<N_POST / RPB, 128>>>(out);
}

// round 12
// speedup vs baseline: 1.0767x; 1.0767x over previous
#include <cuda_runtime.h>
#include <cuda_fp16.h>

#define S        128
#define N_LGN    17400
#define N_POST   50000
#define NNZ      800000
#define NBASIS   5
#define N_RECEPT 10
#define OUT_ROW  (N_POST * NBASIS)   // 250000
#define RPB      8                   // rows per block (spmm)
#define CAP      64                  // bucket capacity (Poisson(16); P(>64) ~ 1e-32)
#define PREP_BLKS 544                // ceil(17400/32)
#define SCAT_BLKS ((NNZ + 511) / 512)

// ---------------- device scratch (no allocations allowed) ----------------
// xTh: uint2 at [c*32 + lane] = 4 halves x[s = {lane, lane+32, lane+64, lane+96}][c]
// g_cnt invariant: zero at entry of every kernel_launch (module-load zero init;
// k_spmm re-zeros each row after reading it).
__device__ __half g_xTh[N_LGN * S];
__device__ int    g_cnt[N_POST];
__device__ int4   g_meta[(size_t)N_POST * CAP];  // {col*256, sid*48, w_bits, 0}

typedef unsigned long long ull;
__device__ __forceinline__ void ffma2(ull &d, ull a, ull b) {
    asm("fma.rn.f32x2 %0, %1, %2, %0;" : "+l"(d) : "l"(a), "l"(b));
}
__device__ __forceinline__ ull pack2(float x, float y) {
    ull r;
    asm("mov.b64 %0, {%1, %2};" : "=l"(r) : "f"(x), "f"(y));
    return r;
}
__device__ __forceinline__ float2 unpack2(ull v) {
    float2 f;
    asm("mov.b64 {%0, %1}, %2;" : "=f"(f.x), "=f"(f.y) : "l"(v));
    return f;
}

// ------------- 1) fused: transpose/pack x  ||  bucket scatter -------------
__global__ void __launch_bounds__(512) k_pre(const float* __restrict__ x,
                                             const int2*  __restrict__ idx,
                                             const float* __restrict__ w,
                                             const int*   __restrict__ sids) {
    __shared__ float tile[S][33];
    int tid = threadIdx.x;

    if (blockIdx.x < PREP_BLKS) {
        // ---- transpose x[s][c] -> permuted fp16 pack ----
        int tx = tid & 31, ty = tid >> 5;    // (32,16)
        int c0 = blockIdx.x * 32;
        int c = c0 + tx;
        bool cok = (c < N_LGN);
        #pragma unroll
        for (int j = ty; j < S; j += 16)
            tile[j][tx] = cok ? x[j * N_LGN + c] : 0.f;
        __syncthreads();

        uint2* xb = (uint2*)g_xTh;
        #pragma unroll
        for (int cl = ty; cl < 32; cl += 16) {
            int cc = c0 + cl;
            if (cc < N_LGN) {
                __half2 h01 = __floats2half2_rn(tile[tx][cl],      tile[tx + 32][cl]);
                __half2 h23 = __floats2half2_rn(tile[tx + 64][cl], tile[tx + 96][cl]);
                uint2 v;
                v.x = *(unsigned int*)&h01;
                v.y = *(unsigned int*)&h23;
                xb[cc * 32 + tx] = v;
            }
        }
    } else {
        // ---- scatter: 16B meta, offsets premultiplied ----
        int e = (blockIdx.x - PREP_BLKS) * 512 + tid;
        if (e >= NNZ) return;
        int2 rc = idx[e];
        int p = atomicAdd(&g_cnt[rc.x], 1);
        if (p < CAP)
            g_meta[(size_t)rc.x * CAP + p] =
                make_int4(rc.y * 256, sids[e] * 48, __float_as_int(w[e]), 0);
    }
}

// ---------------- per-edge math: 3 LDS + 2 FMUL2 + 10 FFMA2 ----------------
__device__ __forceinline__ void edge_math(unsigned fa, int w_bits, uint2 xh,
                                          ull acc[NBASIS][2]) {
    float w = __int_as_float(w_bits);
    float2 x01 = __half22float2(*(__half2*)&xh.x);   // s = lane, lane+32
    float2 x23 = __half22float2(*(__half2*)&xh.y);   // s = lane+64, lane+96
    ull ww, xwa, xwc;
    asm("mov.b64 %0, {%1, %1};" : "=l"(ww) : "f"(w));
    ull xa = pack2(x01.x, x01.y);
    ull xc = pack2(x23.x, x23.y);
    asm("mul.rn.f32x2 %0, %1, %2;" : "=l"(xwa) : "l"(xa), "l"(ww));
    asm("mul.rn.f32x2 %0, %1, %2;" : "=l"(xwc) : "l"(xc), "l"(ww));
    ull f0, f1, f2, f3, f4;
    asm("ld.shared.v2.u64 {%0, %1}, [%2];"      : "=l"(f0), "=l"(f1) : "r"(fa));
    asm("ld.shared.v2.u64 {%0, %1}, [%2 + 16];" : "=l"(f2), "=l"(f3) : "r"(fa));
    asm("ld.shared.u64 %0, [%1 + 32];"          : "=l"(f4) : "r"(fa));
    ffma2(acc[0][0], xwa, f0); ffma2(acc[0][1], xwc, f0);
    ffma2(acc[1][0], xwa, f1); ffma2(acc[1][1], xwc, f1);
    ffma2(acc[2][0], xwa, f2); ffma2(acc[2][1], xwc, f2);
    ffma2(acc[3][0], xwa, f3); ffma2(acc[3][1], xwc, f3);
    ffma2(acc[4][0], xwa, f4); ffma2(acc[4][1], xwc, f4);
}

// ---------------- 2) main SpMM: 128 thr, 4 warps x 2 rows ----------------
__global__ void __launch_bounds__(128, 8) k_spmm(float* __restrict__ out,
                                                 const float* __restrict__ synw) {
    // staging transposed: sg[j][s], j = rowlocal*5 + r; 129-word rows => the
    // 20 STS per row hit consecutive banks (conflict-free; was 4-way at stride 44)
    __shared__ float sg[RPB * NBASIS][129];
    __shared__ __align__(16) float2 fsh2[N_RECEPT * 6];  // dup pairs, 48B per sid
    int tid = threadIdx.x;
    if (tid < N_RECEPT * 6) {
        int sid = tid / 6, r = tid - sid * 6;
        float v = (r < NBASIS) ? synw[sid * NBASIS + r] : 0.f;
        fsh2[tid] = make_float2(v, v);
    }
    __syncthreads();
    unsigned fbase = (unsigned)__cvta_generic_to_shared(fsh2);

    int warp = tid >> 5;
    int lane = tid & 31;
    int n0 = blockIdx.x * RPB;
    const char* xlane = (const char*)g_xTh + lane * 8;

    #pragma unroll
    for (int rr = 0; rr < 2; rr++) {
        int n = n0 + warp * 2 + rr;
        int len = g_cnt[n];
        if (lane == 0) g_cnt[n] = 0;      // restore invariant for next replay
        if (len > CAP) len = CAP;
        const int4* pm = g_meta + (size_t)n * CAP;

        ull acc[NBASIS][2];
        #pragma unroll
        for (int r = 0; r < NBASIS; r++) { acc[r][0] = 0ull; acc[r][1] = 0ull; }

        for (int seg = 0; seg * 32 < len; seg++) {
            int4 m = __ldg(pm + seg * 32 + lane);   // 32 edges' meta in warp regs
            int cnt = len - seg * 32;
            if (cnt > 32) cnt = 32;

            int j = 0;
            #pragma unroll 1
            for (; j + 4 <= cnt; j += 4) {
                uint2 xv[4];
                #pragma unroll
                for (int t = 0; t < 4; t++) {
                    int mx = __shfl_sync(0xFFFFFFFFu, m.x, j + t);
                    xv[t] = __ldg((const uint2*)(xlane + mx));   // MLP 4
                }
                #pragma unroll
                for (int t = 0; t < 4; t++) {
                    int my = __shfl_sync(0xFFFFFFFFu, m.y, j + t);
                    int mw = __shfl_sync(0xFFFFFFFFu, m.z, j + t);
                    edge_math(fbase + (unsigned)my, mw, xv[t], acc);
                }
            }
            for (; j < cnt; j++) {
                int mx = __shfl_sync(0xFFFFFFFFu, m.x, j);
                int my = __shfl_sync(0xFFFFFFFFu, m.y, j);
                int mw = __shfl_sync(0xFFFFFFFFu, m.z, j);
                uint2 xv = __ldg((const uint2*)(xlane + mx));
                edge_math(fbase + (unsigned)my, mw, xv, acc);
            }
        }

        // stage row (conflict-free: consecutive lanes -> consecutive banks)
        int rl = (warp * 2 + rr) * NBASIS;
        #pragma unroll
        for (int r = 0; r < NBASIS; r++) {
            float2 lo = unpack2(acc[r][0]);
            float2 hi = unpack2(acc[r][1]);
            sg[rl + r][lane      ] = lo.x;
            sg[rl + r][lane + 32 ] = lo.y;
            sg[rl + r][lane + 64 ] = hi.x;
            sg[rl + r][lane + 96 ] = hi.y;
        }
    }
    __syncthreads();

    // write-out: gather 4 scalars per thread -> one float4 STG (160B/s-row)
    float* op = out + (size_t)n0 * NBASIS;
    #pragma unroll
    for (int it = 0; it < 10; it++) {
        int idx = it * 128 + tid;       // 1280 float4 total
        int s = idx / 10;
        int q = idx - s * 10;           // q-th float4 of this s-row
        float4 v = make_float4(sg[q * 4    ][s], sg[q * 4 + 1][s],
                               sg[q * 4 + 2][s], sg[q * 4 + 3][s]);
        *(float4*)(op + (size_t)s * OUT_ROW + q * 4) = v;
    }
}

// ---------------- launch ----------------
extern "C" void kernel_launch(void* const* d_in, const int* in_sizes, int n_in,
                              void* d_out, int out_size) {
    const float* inp     = (const float*)d_in[0];
    const int2*  indices = (const int2*)d_in[1];
    const float* weights = (const float*)d_in[2];
    const float* synw    = (const float*)d_in[3];
    const int*   sids    = (const int*)d_in[4];
    float*       out     = (float*)d_out;
    (void)in_sizes; (void)n_in; (void)out_size;

    k_pre<<<PREP_BLKS + SCAT_BLKS, 512>>>(inp, indices, weights, sids);
    k_spmm<<<N_POST / RPB, 128>>>(out, synw);
}

// round 13
// speedup vs baseline: 1.5159x; 1.4079x over previous
#include <cuda_runtime.h>
#include <cuda_fp16.h>

#define S        128
#define N_LGN    17400
#define N_POST   50000
#define NNZ      800000
#define NBASIS   5
#define N_RECEPT 10
#define OUT_ROW  (N_POST * NBASIS)   // 250000
#define RPB      8                   // rows per block
#define CAP      64                  // bucket capacity (Poisson(16); P(>64) ~ 1e-32)
#define PREP_BLKS 544                // ceil(17400/32)
#define SCAT_BLKS ((NNZ + 511) / 512)

// ---------------- device scratch (no allocations allowed) ----------------
// xTh layout: uint2 at [c*32 + lane] = 4 halves x[s = {lane, lane+32, lane+64, lane+96}][c]
__device__ __half g_xTh[N_LGN * S];
__device__ int    g_cnt[N_POST];
__device__ int4   g_meta[(size_t)N_POST * CAP];  // {col*256, sid*48, w_bits, 0}

typedef unsigned long long ull;
__device__ __forceinline__ void ffma2(ull &d, ull a, ull b) {
    asm("fma.rn.f32x2 %0, %1, %2, %0;" : "+l"(d) : "l"(a), "l"(b));
}
__device__ __forceinline__ ull pack2(float x, float y) {
    ull r;
    asm("mov.b64 %0, {%1, %2};" : "=l"(r) : "f"(x), "f"(y));
    return r;
}
__device__ __forceinline__ float2 unpack2(ull v) {
    float2 f;
    asm("mov.b64 {%0, %1}, %2;" : "=f"(f.x), "=f"(f.y) : "l"(v));
    return f;
}

// ---------------- 0) zero counters (must precede scatter atomics) ----------
__global__ void k_zero() {
    int i = blockIdx.x * blockDim.x + threadIdx.x;
    if (i < N_POST) g_cnt[i] = 0;
}

// ------------- 1) fused: transpose/pack x  ||  bucket scatter -------------
__global__ void __launch_bounds__(512) k_pre(const float* __restrict__ x,
                                             const int2*  __restrict__ idx,
                                             const float* __restrict__ w,
                                             const int*   __restrict__ sids) {
    __shared__ float tile[S][33];
    int tid = threadIdx.x;

    if (blockIdx.x < PREP_BLKS) {
        // ---- transpose x[s][c] -> permuted fp16 pack ----
        int tx = tid & 31, ty = tid >> 5;    // (32,16)
        int c0 = blockIdx.x * 32;
        int c = c0 + tx;
        bool cok = (c < N_LGN);
        #pragma unroll
        for (int j = ty; j < S; j += 16)
            tile[j][tx] = cok ? x[j * N_LGN + c] : 0.f;
        __syncthreads();

        uint2* xb = (uint2*)g_xTh;
        #pragma unroll
        for (int cl = ty; cl < 32; cl += 16) {
            int cc = c0 + cl;
            if (cc < N_LGN) {
                __half2 h01 = __floats2half2_rn(tile[tx][cl],      tile[tx + 32][cl]);
                __half2 h23 = __floats2half2_rn(tile[tx + 64][cl], tile[tx + 96][cl]);
                uint2 v;
                v.x = *(unsigned int*)&h01;
                v.y = *(unsigned int*)&h23;
                xb[cc * 32 + tx] = v;
            }
        }
    } else {
        // ---- scatter: 16B meta, offsets premultiplied ----
        int e = (blockIdx.x - PREP_BLKS) * 512 + tid;
        if (e >= NNZ) return;
        int2 rc = idx[e];
        int p = atomicAdd(&g_cnt[rc.x], 1);
        if (p < CAP)
            g_meta[(size_t)rc.x * CAP + p] =
                make_int4(rc.y * 256, sids[e] * 48, __float_as_int(w[e]), 0);
    }
}

// ---------------- per-edge math (EXACT R10 source — do not perturb) --------
__device__ __forceinline__ void edge_math(unsigned fa, int w_bits, uint2 xh,
                                          ull acc[NBASIS][2]) {
    float w = __int_as_float(w_bits);
    float2 x01 = __half22float2(*(__half2*)&xh.x);   // s = lane, lane+32
    float2 x23 = __half22float2(*(__half2*)&xh.y);   // s = lane+64, lane+96
    ull ww, xwa, xwc;
    asm("mov.b64 %0, {%1, %1};" : "=l"(ww) : "f"(w));
    ull xa = pack2(x01.x, x01.y);
    ull xc = pack2(x23.x, x23.y);
    asm("mul.rn.f32x2 %0, %1, %2;" : "=l"(xwa) : "l"(xa), "l"(ww));
    asm("mul.rn.f32x2 %0, %1, %2;" : "=l"(xwc) : "l"(xc), "l"(ww));
    ull f0, f1, f2, f3, f4;
    asm("ld.shared.v2.u64 {%0, %1}, [%2];"      : "=l"(f0), "=l"(f1) : "r"(fa));
    asm("ld.shared.v2.u64 {%0, %1}, [%2 + 16];" : "=l"(f2), "=l"(f3) : "r"(fa));
    asm("ld.shared.u64 %0, [%1 + 32];"          : "=l"(f4) : "r"(fa));
    ffma2(acc[0][0], xwa, f0); ffma2(acc[0][1], xwc, f0);
    ffma2(acc[1][0], xwa, f1); ffma2(acc[1][1], xwc, f1);
    ffma2(acc[2][0], xwa, f2); ffma2(acc[2][1], xwc, f2);
    ffma2(acc[3][0], xwa, f3); ffma2(acc[3][1], xwc, f3);
    ffma2(acc[4][0], xwa, f4); ffma2(acc[4][1], xwc, f4);
}

// ---------------- 2) main SpMM (EXACT R10 source — do not perturb) ---------
__global__ void __launch_bounds__(128, 8) k_spmm(float* __restrict__ out,
                                                 const float* __restrict__ synw) {
    __shared__ __align__(16) float  sh[S * 44];          // stride 44: 16B-aligned rows
    __shared__ __align__(16) float2 fsh2[N_RECEPT * 6];  // dup pairs, 48B per sid
    int tid = threadIdx.x;
    if (tid < N_RECEPT * 6) {
        int sid = tid / 6, r = tid - sid * 6;
        float v = (r < NBASIS) ? synw[sid * NBASIS + r] : 0.f;
        fsh2[tid] = make_float2(v, v);
    }
    __syncthreads();
    unsigned fbase = (unsigned)__cvta_generic_to_shared(fsh2);

    int warp = tid >> 5;
    int lane = tid & 31;
    int n0 = blockIdx.x * RPB;
    const char* xlane = (const char*)g_xTh + lane * 8;

    #pragma unroll
    for (int rr = 0; rr < 2; rr++) {
        int n = n0 + warp * 2 + rr;
        int len = g_cnt[n];
        if (len > CAP) len = CAP;
        const int4* pm = g_meta + (size_t)n * CAP;

        ull acc[NBASIS][2];
        #pragma unroll
        for (int r = 0; r < NBASIS; r++) { acc[r][0] = 0ull; acc[r][1] = 0ull; }

        for (int seg = 0; seg * 32 < len; seg++) {
            int4 m = __ldg(pm + seg * 32 + lane);   // 32 edges' meta in warp regs
            int cnt = len - seg * 32;
            if (cnt > 32) cnt = 32;

            int j = 0;
            #pragma unroll 1
            for (; j + 4 <= cnt; j += 4) {
                uint2 xv[4];
                #pragma unroll
                for (int t = 0; t < 4; t++) {
                    int mx = __shfl_sync(0xFFFFFFFFu, m.x, j + t);
                    xv[t] = __ldg((const uint2*)(xlane + mx));   // MLP 4, 2 wf each
                }
                #pragma unroll
                for (int t = 0; t < 4; t++) {
                    int my = __shfl_sync(0xFFFFFFFFu, m.y, j + t);
                    int mw = __shfl_sync(0xFFFFFFFFu, m.z, j + t);
                    edge_math(fbase + (unsigned)my, mw, xv[t], acc);
                }
            }
            for (; j < cnt; j++) {
                int mx = __shfl_sync(0xFFFFFFFFu, m.x, j);
                int my = __shfl_sync(0xFFFFFFFFu, m.y, j);
                int mw = __shfl_sync(0xFFFFFFFFu, m.z, j);
                uint2 xv = __ldg((const uint2*)(xlane + mx));
                edge_math(fbase + (unsigned)my, mw, xv, acc);
            }
        }

        // stage row (warp*2+rr): lane's values are s = {lane, +32, +64, +96}
        int rl = (warp * 2 + rr) * NBASIS;
        #pragma unroll
        for (int r = 0; r < NBASIS; r++) {
            float2 lo = unpack2(acc[r][0]);
            float2 hi = unpack2(acc[r][1]);
            sh[(lane      ) * 44 + rl + r] = lo.x;
            sh[(lane + 32 ) * 44 + rl + r] = lo.y;
            sh[(lane + 64 ) * 44 + rl + r] = hi.x;
            sh[(lane + 96 ) * 44 + rl + r] = hi.y;
        }
    }
    __syncthreads();

    // vectorized write-out: 1280 float4 = 128 s x 10 q; 10 iters per thread
    const float4* sh4 = (const float4*)sh;           // 11 float4 per s-row
    float* op = out + (size_t)n0 * NBASIS;
    #pragma unroll
    for (int it = 0; it < 10; it++) {
        int idx = it * 128 + tid;
        int s = idx / 10;
        int q = idx - s * 10;
        float4 v = sh4[s * 11 + q];
        *(float4*)(op + (size_t)s * OUT_ROW + q * 4) = v;
    }
}

// ---------------- launch ----------------
extern "C" void kernel_launch(void* const* d_in, const int* in_sizes, int n_in,
                              void* d_out, int out_size) {
    const float* inp     = (const float*)d_in[0];
    const int2*  indices = (const int2*)d_in[1];
    const float* weights = (const float*)d_in[2];
    const float* synw    = (const float*)d_in[3];
    const int*   sids    = (const int*)d_in[4];
    float*       out     = (float*)d_out;
    (void)in_sizes; (void)n_in; (void)out_size;

    k_zero<<<(N_POST + 255) / 256, 256>>>();
    k_pre<<<PREP_BLKS + SCAT_BLKS, 512>>>(inp, indices, weights, sids);
    k_spmm<<<N_POST / RPB, 128>>>(out, synw);
}